// round 3
// baseline (speedup 1.0000x reference)
#include <cuda_runtime.h>
#include <math.h>

// Problem constants
#define R_TOTAL 131072          // B*N = 8*16384 flattened rows
#define DIMV    512
#define HEADS   8
#define DH      64
#define KR      4
#define BM      32              // rows per block

// Scratch (allocation-free rule: __device__ globals)
__device__ float g_q[(size_t)R_TOTAL * 32];   // q-hat, [row][h*4+r], 16 MB
__device__ float g_kv[16384];                 // [b][h][r][c] unnormalized then normalized
__device__ float g_ksum[256];                 // [b][h][r]

// ---------- packed f32x2 helpers (sm_10x FFMA2) ----------
__device__ __forceinline__ unsigned long long pack2f(float lo, float hi) {
    unsigned long long r;
    asm("mov.b64 %0, {%1,%2};" : "=l"(r) : "f"(lo), "f"(hi));
    return r;
}
__device__ __forceinline__ void unpack2f(unsigned long long v, float &lo, float &hi) {
    asm("mov.b64 {%0,%1}, %2;" : "=f"(lo), "=f"(hi) : "l"(v));
}
__device__ __forceinline__ void ffma2(unsigned long long &d, unsigned long long a, unsigned long long b) {
    asm("fma.rn.f32x2 %0, %1, %2, %0;" : "+l"(d) : "l"(a), "l"(b));
}

// ---------- zero the kv accumulators ----------
__global__ void k_zero() {
    int i = blockIdx.x * 256 + threadIdx.x;
    if (i < 16384) g_kv[i] = 0.0f;
    if (i < 256)   g_ksum[i] = 0.0f;
}

// ---------- kernel 1: x_mid GEMM + fused q/k/v epilogue + kv reduction ----------
// smem layout (floats):
//   xs   [0,       16384)  : 32x512 x tile; reused as vbuf in epilogue
//   ms   [16384,   32768)  : 32x512 x_mid tile
//   ws   [32768,   36864)  : 32x128 W_in tile; reused as W_v (64x64) in epilogue
//   eks  [36864,   37888)  : 32x32 exp(k) per row
//   wqk  [37888,   38400)  : W_q (256) then W_k (256)
#define SMEM1_FLOATS 38400

__global__ __launch_bounds__(256)
void k1(const float* __restrict__ x, const float* __restrict__ Win,
        const float* __restrict__ bin, const float* __restrict__ Wq,
        const float* __restrict__ Wk, const float* __restrict__ Wv)
{
    extern __shared__ float sm[];
    float* xs  = sm;
    float* ms  = sm + 16384;
    float* ws  = sm + 32768;
    float* eks = sm + 36864;
    float* wqk = sm + 37888;

    const int tid = threadIdx.x;
    const int br  = blockIdx.x;
    const float* xg = x + (size_t)br * BM * DIMV;

    // load x tile (32x512) into smem
    {
        const float4* src = (const float4*)xg;
        float4* dst = (float4*)xs;
        for (int i = tid; i < 4096; i += 256) dst[i] = src[i];
    }
    // load W_q / W_k (64x4 each)
    if (tid < 256) { wqk[tid] = Wq[tid]; wqk[256 + tid] = Wk[tid]; }
    __syncthreads();

    const int row = tid >> 3;     // 0..31
    const int cg  = tid & 7;      // 0..7, 16 cols each

    // GEMM: x_mid = x @ W_in + b_in, in 4 column chunks of 128
    for (int ch = 0; ch < 4; ch++) {
        const int c0 = ch * 128;
        unsigned long long acc[8];
        #pragma unroll
        for (int p = 0; p < 8; p++) acc[p] = 0ull;

        for (int k0 = 0; k0 < 512; k0 += 32) {
            // stage W_in[k0..k0+31][c0..c0+127] -> ws (32x128)
            for (int i = tid; i < 1024; i += 256) {
                int kk = i >> 5, c4 = i & 31;
                ((float4*)ws)[i] = *(const float4*)&Win[(size_t)(k0 + kk) * DIMV + c0 + c4 * 4];
            }
            __syncthreads();
            #pragma unroll
            for (int kk = 0; kk < 32; kk++) {
                float a = xs[row * DIMV + k0 + kk];
                unsigned long long a2 = pack2f(a, a);
                const ulonglong2* bp = (const ulonglong2*)(ws + kk * 128 + cg * 16);
                ulonglong2 b0 = bp[0], b1 = bp[1], b2 = bp[2], b3 = bp[3];
                ffma2(acc[0], a2, b0.x); ffma2(acc[1], a2, b0.y);
                ffma2(acc[2], a2, b1.x); ffma2(acc[3], a2, b1.y);
                ffma2(acc[4], a2, b2.x); ffma2(acc[5], a2, b2.y);
                ffma2(acc[6], a2, b3.x); ffma2(acc[7], a2, b3.y);
            }
            __syncthreads();
        }
        // bias + store x_mid chunk
        #pragma unroll
        for (int p = 0; p < 8; p++) {
            float lo, hi; unpack2f(acc[p], lo, hi);
            int c = c0 + cg * 16 + p * 2;
            ms[row * DIMV + c]     = lo + bin[c];
            ms[row * DIMV + c + 1] = hi + bin[c + 1];
        }
    }
    __syncthreads();

    // ---------------- epilogue: thread owns (row=erow, head=h) ----------------
    const int erow = tid >> 3;
    const int h    = tid & 7;

    // x_mid head slice into registers
    float xm[64];
    {
        const float* p = &ms[erow * DIMV + h * DH];
        #pragma unroll
        for (int d = 0; d < 64; d++) xm[d] = p[d];
    }

    // q / k logits (W_q, W_k broadcast across all threads)
    float ql[4] = {0.f, 0.f, 0.f, 0.f};
    float kl[4] = {0.f, 0.f, 0.f, 0.f};
    #pragma unroll
    for (int d = 0; d < 64; d++) {
        float a = xm[d];
        #pragma unroll
        for (int r = 0; r < 4; r++) {
            ql[r] += a * wqk[d * 4 + r];
            kl[r] += a * wqk[256 + d * 4 + r];
        }
    }
    // q softmax over r=4, store q-hat
    {
        float qm = fmaxf(fmaxf(ql[0], ql[1]), fmaxf(ql[2], ql[3]));
        float e0 = expf(ql[0] - qm), e1 = expf(ql[1] - qm);
        float e2 = expf(ql[2] - qm), e3 = expf(ql[3] - qm);
        float inv = 1.0f / (e0 + e1 + e2 + e3);
        size_t g = (size_t)br * BM + erow;
        g_q[g * 32 + h * 4 + 0] = e0 * inv;
        g_q[g * 32 + h * 4 + 1] = e1 * inv;
        g_q[g * 32 + h * 4 + 2] = e2 * inv;
        g_q[g * 32 + h * 4 + 3] = e3 * inv;
    }
    // exp(k) (no max-shift needed: |k| small) into smem
    eks[erow * 32 + h * 4 + 0] = expf(kl[0]);
    eks[erow * 32 + h * 4 + 1] = expf(kl[1]);
    eks[erow * 32 + h * 4 + 2] = expf(kl[2]);
    eks[erow * 32 + h * 4 + 3] = expf(kl[3]);

    // stage W_v (64x64) into ws (all prior ws readers passed a sync already)
    for (int i = tid; i < 1024; i += 256)
        ((float4*)ws)[i] = ((const float4*)Wv)[i];
    __syncthreads();

    // v = xm @ W_v -> vbuf (reuse xs)
    float* vbuf = xs;
    #pragma unroll
    for (int pass = 0; pass < 4; pass++) {
        unsigned long long vacc[8];
        #pragma unroll
        for (int p = 0; p < 8; p++) vacc[p] = 0ull;
        const int cb = pass * 16;
        #pragma unroll
        for (int d = 0; d < 64; d++) {
            unsigned long long a2 = pack2f(xm[d], xm[d]);
            const ulonglong2* wp = (const ulonglong2*)(ws + d * DH + cb);
            ulonglong2 w0 = wp[0], w1 = wp[1], w2 = wp[2], w3 = wp[3];
            ffma2(vacc[0], a2, w0.x); ffma2(vacc[1], a2, w0.y);
            ffma2(vacc[2], a2, w1.x); ffma2(vacc[3], a2, w1.y);
            ffma2(vacc[4], a2, w2.x); ffma2(vacc[5], a2, w2.y);
            ffma2(vacc[6], a2, w3.x); ffma2(vacc[7], a2, w3.y);
        }
        #pragma unroll
        for (int p = 0; p < 8; p++) {
            float lo, hi; unpack2f(vacc[p], lo, hi);
            vbuf[erow * DIMV + h * DH + cb + p * 2]     = lo;
            vbuf[erow * DIMV + h * DH + cb + p * 2 + 1] = hi;
        }
    }
    __syncthreads();

    // block-level kv partial reduction, then global atomic accumulate
    const int b = (br * BM) >> 14;   // batch index (16384 rows per batch)
    for (int o = tid; o < 2048; o += 256) {
        int hh = o >> 8, rr = (o >> 6) & 3, cc = o & 63;
        float s = 0.f;
        #pragma unroll
        for (int rw = 0; rw < 32; rw++)
            s += eks[rw * 32 + hh * 4 + rr] * vbuf[rw * DIMV + hh * DH + cc];
        atomicAdd(&g_kv[((b * 8 + hh) * 4 + rr) * 64 + cc], s);
    }
    if (tid < 32) {
        int hh = tid >> 2, rr = tid & 3;
        float s = 0.f;
        #pragma unroll
        for (int rw = 0; rw < 32; rw++) s += eks[rw * 32 + hh * 4 + rr];
        atomicAdd(&g_ksum[(b * 8 + hh) * 4 + rr], s);
    }
}

// ---------- kernel 2: normalize kv by column-softmax denominator ----------
__global__ void k_norm() {
    int i = blockIdx.x * 256 + threadIdx.x;
    if (i < 16384) g_kv[i] = g_kv[i] / g_ksum[i >> 6];
}

// ---------- kernel 3: qkv = q-hat @ kv, then out = qkv @ W_out + b_out ----------
// smem layout (floats):
//   qs  [0,     16384) : 32x512 qkv tile
//   ws  [16384, 20480) : 32x128 W_out tile
//   qh  [20480, 21504) : 32x32 q-hat
//   kvs [21504, 23552) : 8x4x64 kv for this batch
#define SMEM3_FLOATS 23552

__global__ __launch_bounds__(256)
void k3(const float* __restrict__ Wout, const float* __restrict__ bout,
        float* __restrict__ out)
{
    extern __shared__ float sm[];
    float* qs  = sm;
    float* ws  = sm + 16384;
    float* qh  = sm + 20480;
    float* kvs = sm + 21504;

    const int tid = threadIdx.x;
    const int br  = blockIdx.x;
    const int b   = (br * BM) >> 14;

    // load q-hat rows and this batch's kv
    {
        const float4* src = (const float4*)(g_q + (size_t)br * BM * 32);
        for (int i = tid; i < 256; i += 256) ((float4*)qh)[i] = src[i];
        const float4* kvsrc = (const float4*)(g_kv + b * 2048);
        for (int i = tid; i < 512; i += 256) ((float4*)kvs)[i] = kvsrc[i];
    }
    __syncthreads();

    // build qkv rows: thread owns (row, head)
    {
        const int row = tid >> 3, h = tid & 7;
        float q0 = qh[row * 32 + h * 4 + 0];
        float q1 = qh[row * 32 + h * 4 + 1];
        float q2 = qh[row * 32 + h * 4 + 2];
        float q3 = qh[row * 32 + h * 4 + 3];
        const float4* kp = (const float4*)kvs + (h * 4) * 16;
        #pragma unroll
        for (int c4 = 0; c4 < 16; c4++) {
            float4 a0 = kp[0 * 16 + c4], a1 = kp[1 * 16 + c4];
            float4 a2 = kp[2 * 16 + c4], a3 = kp[3 * 16 + c4];
            float4 o;
            o.x = q0 * a0.x + q1 * a1.x + q2 * a2.x + q3 * a3.x;
            o.y = q0 * a0.y + q1 * a1.y + q2 * a2.y + q3 * a3.y;
            o.z = q0 * a0.z + q1 * a1.z + q2 * a2.z + q3 * a3.z;
            o.w = q0 * a0.w + q1 * a1.w + q2 * a2.w + q3 * a3.w;
            ((float4*)qs)[row * 128 + h * 16 + c4] = o;
        }
    }
    __syncthreads();

    // GEMM: out = qs @ W_out + b_out
    const int row = tid >> 3;
    const int cg  = tid & 7;
    float* og = out + (size_t)br * BM * DIMV;

    for (int ch = 0; ch < 4; ch++) {
        const int c0 = ch * 128;
        unsigned long long acc[8];
        #pragma unroll
        for (int p = 0; p < 8; p++) acc[p] = 0ull;

        for (int k0 = 0; k0 < 512; k0 += 32) {
            for (int i = tid; i < 1024; i += 256) {
                int kk = i >> 5, c4 = i & 31;
                ((float4*)ws)[i] = *(const float4*)&Wout[(size_t)(k0 + kk) * DIMV + c0 + c4 * 4];
            }
            __syncthreads();
            #pragma unroll
            for (int kk = 0; kk < 32; kk++) {
                float a = qs[row * DIMV + k0 + kk];
                unsigned long long a2 = pack2f(a, a);
                const ulonglong2* bp = (const ulonglong2*)(ws + kk * 128 + cg * 16);
                ulonglong2 b0 = bp[0], b1 = bp[1], b2 = bp[2], b3 = bp[3];
                ffma2(acc[0], a2, b0.x); ffma2(acc[1], a2, b0.y);
                ffma2(acc[2], a2, b1.x); ffma2(acc[3], a2, b1.y);
                ffma2(acc[4], a2, b2.x); ffma2(acc[5], a2, b2.y);
                ffma2(acc[6], a2, b3.x); ffma2(acc[7], a2, b3.y);
            }
            __syncthreads();
        }
        #pragma unroll
        for (int p = 0; p < 8; p++) {
            float lo, hi; unpack2f(acc[p], lo, hi);
            int c = c0 + cg * 16 + p * 2;
            og[(size_t)row * DIMV + c]     = lo + bout[c];
            og[(size_t)row * DIMV + c + 1] = hi + bout[c + 1];
        }
    }
}

// ---------- launch ----------
extern "C" void kernel_launch(void* const* d_in, const int* in_sizes, int n_in,
                              void* d_out, int out_size)
{
    const float* x    = (const float*)d_in[0];
    const float* Win  = (const float*)d_in[1];
    const float* bin  = (const float*)d_in[2];
    const float* Wq   = (const float*)d_in[3];
    const float* Wk   = (const float*)d_in[4];
    const float* Wv   = (const float*)d_in[5];
    const float* Wout = (const float*)d_in[6];
    const float* bout = (const float*)d_in[7];
    float* out = (float*)d_out;

    cudaFuncSetAttribute(k1, cudaFuncAttributeMaxDynamicSharedMemorySize, SMEM1_FLOATS * 4);
    cudaFuncSetAttribute(k3, cudaFuncAttributeMaxDynamicSharedMemorySize, SMEM3_FLOATS * 4);

    const int nblocks = R_TOTAL / BM;   // 4096
    k_zero<<<64, 256>>>();
    k1<<<nblocks, 256, SMEM1_FLOATS * 4>>>(x, Win, bin, Wq, Wk, Wv);
    k_norm<<<64, 256>>>();
    k3<<<nblocks, 256, SMEM3_FLOATS * 4>>>(Wout, bout, out);
}

// round 5
// speedup vs baseline: 23.7610x; 23.7610x over previous
#include <cuda_runtime.h>
#include <math.h>

#define NB    8
#define RTOT  131072
#define DX    512
#define MT    128
#define GRID_MAIN (RTOT/MT)   // 1024

// ---------------- device scratch ----------------
__device__ float g_Wqk[DX*64];
__device__ float g_bqk[64];
__device__ float g_q[(size_t)RTOT*32];   // q-hat [n][h*4+r]
__device__ float g_S[NB*32*DX];          // S_b[hr][i] = sum_n ek*x
__device__ float g_ksum[NB*32];
__device__ float g_T[NB*32*64];
__device__ float g_kvn[NB*32*64];
__device__ float g_M2[NB*32*DX];

// ---------------- packed f32x2 helpers ----------------
__device__ __forceinline__ unsigned long long pack2f(float lo, float hi){
    unsigned long long r; asm("mov.b64 %0,{%1,%2};":"=l"(r):"f"(lo),"f"(hi)); return r;}
__device__ __forceinline__ void unpack2f(unsigned long long v, float&lo, float&hi){
    asm("mov.b64 {%0,%1},%2;":"=f"(lo),"=f"(hi):"l"(v));}
__device__ __forceinline__ void ffma2(unsigned long long&d, unsigned long long a, unsigned long long b){
    asm("fma.rn.f32x2 %0,%1,%2,%0;":"+l"(d):"l"(a),"l"(b));}
__device__ __forceinline__ float f4c(const float4&v,int t){
    return t==0?v.x: t==1?v.y: t==2?v.z: v.w;}

// ---------------- zero accumulators ----------------
__global__ void k_zero(){
    int i = blockIdx.x*256 + threadIdx.x;
    if (i < NB*32*DX) g_S[i] = 0.0f;
    if (i < NB*32)    g_ksum[i] = 0.0f;
}

// ---------------- fold weights: Wqkc = Win @ blkdiag(Wq|Wk) ----------------
__global__ void k_combine(const float* __restrict__ Win, const float* __restrict__ bin,
                          const float* __restrict__ Wq,  const float* __restrict__ Wk){
    int idx = blockIdx.x*256 + threadIdx.x;
    if (idx < DX*64){
        int i = idx >> 6, j = idx & 63;
        int h = (j >> 2) & 7, r = j & 3;
        const float* W = (j < 32) ? Wq : Wk;
        float s = 0.f;
        #pragma unroll 8
        for (int d = 0; d < 64; d++) s += Win[(size_t)i*DX + h*64 + d] * W[d*4 + r];
        g_Wqk[i*64 + j] = s;
    } else if (idx < DX*64 + 64){
        int j = idx - DX*64;
        int h = (j >> 2) & 7, r = j & 3;
        const float* W = (j < 32) ? Wq : Wk;
        float s = 0.f;
        #pragma unroll 8
        for (int d = 0; d < 64; d++) s += bin[h*64 + d] * W[d*4 + r];
        g_bqk[j] = s;
    }
}

// ---------------- main kernel: qk logits + softmax/exp + S accumulation ----------------
// smem floats: xs[128*68]=8704, wq[64*64]=4096, eks[128*33]=4224  -> 17024 (68KB)
#define SM_MAIN 17024

__global__ __launch_bounds__(256)
void k_main(const float* __restrict__ x){
    extern __shared__ float sm[];
    float* xs  = sm;
    float* wq  = sm + 8704;
    float* eks = sm + 12800;

    const int tid = threadIdx.x, blk = blockIdx.x;
    const int rg = tid >> 3, cg = tid & 7;     // 4 rows, 8 cols per thread
    const int row0 = blk * MT;
    const int b = blk >> 7;                    // 128 CTAs per batch

    // -------- pass 1: logits[128x64] = x_tile @ Wqkc --------
    unsigned long long acc[16];
    #pragma unroll
    for (int p = 0; p < 16; p++) acc[p] = 0ull;

    #pragma unroll 1
    for (int ch = 0; ch < 8; ch++){
        __syncthreads();
        for (int idx = tid; idx < 2048; idx += 256){
            int r = idx >> 4, c = idx & 15;
            *(float4*)&xs[r*68 + c*4] =
                *(const float4*)&x[(size_t)(row0 + r)*DX + ch*64 + c*4];
        }
        for (int idx = tid; idx < 1024; idx += 256){
            int k = idx >> 4, c = idx & 15;
            *(float4*)&wq[k*64 + c*4] = *(const float4*)&g_Wqk[(ch*64 + k)*64 + c*4];
        }
        __syncthreads();

        #pragma unroll 1
        for (int kk = 0; kk < 64; kk += 4){
            float4 xv[4];
            #pragma unroll
            for (int rr = 0; rr < 4; rr++)
                xv[rr] = *(float4*)&xs[(rg*4 + rr)*68 + kk];
            #pragma unroll
            for (int t = 0; t < 4; t++){
                ulonglong2 w01 = *(ulonglong2*)&wq[(kk + t)*64 + cg*8];
                ulonglong2 w23 = *(ulonglong2*)&wq[(kk + t)*64 + cg*8 + 4];
                #pragma unroll
                for (int rr = 0; rr < 4; rr++){
                    float a = f4c(xv[rr], t);
                    unsigned long long a2 = pack2f(a, a);
                    ffma2(acc[rr*4+0], a2, w01.x);
                    ffma2(acc[rr*4+1], a2, w01.y);
                    ffma2(acc[rr*4+2], a2, w23.x);
                    ffma2(acc[rr*4+3], a2, w23.y);
                }
            }
        }
    }

    // -------- pass 2: q softmax -> g_q ; exp(k) -> eks --------
    float bj[8];
    #pragma unroll
    for (int o = 0; o < 8; o++) bj[o] = g_bqk[cg*8 + o];

    #pragma unroll
    for (int rr = 0; rr < 4; rr++){
        float v[8];
        #pragma unroll
        for (int p = 0; p < 4; p++) unpack2f(acc[rr*4 + p], v[2*p], v[2*p+1]);
        #pragma unroll
        for (int o = 0; o < 8; o++) v[o] += bj[o];

        int lrow = rg*4 + rr;
        if (cg < 4){
            size_t n = (size_t)row0 + lrow;
            #pragma unroll
            for (int hh = 0; hh < 2; hh++){
                float* p = v + hh*4;
                float m = fmaxf(fmaxf(p[0], p[1]), fmaxf(p[2], p[3]));
                float e0 = expf(p[0]-m), e1 = expf(p[1]-m);
                float e2 = expf(p[2]-m), e3 = expf(p[3]-m);
                float inv = 1.0f/(e0+e1+e2+e3);
                float4 qv; qv.x=e0*inv; qv.y=e1*inv; qv.z=e2*inv; qv.w=e3*inv;
                *(float4*)&g_q[n*32 + cg*8 + hh*4] = qv;
            }
        } else {
            #pragma unroll
            for (int o = 0; o < 8; o++)
                eks[lrow*33 + (cg-4)*8 + o] = expf(v[o]);
        }
    }
    __syncthreads();

    // ksum partials
    if (tid < 32){
        float s = 0.f;
        #pragma unroll 8
        for (int r = 0; r < 128; r++) s += eks[r*33 + tid];
        atomicAdd(&g_ksum[b*32 + tid], s);
    }

    // -------- pass 3: S += eks^T @ x_tile --------
    #pragma unroll 1
    for (int ch = 0; ch < 8; ch++){
        __syncthreads();
        for (int idx = tid; idx < 2048; idx += 256){
            int r = idx >> 4, c = idx & 15;
            *(float4*)&xs[r*68 + c*4] =
                *(const float4*)&x[(size_t)(row0 + r)*DX + ch*64 + c*4];
        }
        __syncthreads();

        const int hr = rg;   // 32 hr values
        unsigned long long sa[4];
        #pragma unroll
        for (int p = 0; p < 4; p++) sa[p] = 0ull;
        #pragma unroll 4
        for (int row = 0; row < 128; row++){
            float e = eks[row*33 + hr];
            unsigned long long e2 = pack2f(e, e);
            ulonglong2 x01 = *(ulonglong2*)&xs[row*68 + cg*8];
            ulonglong2 x23 = *(ulonglong2*)&xs[row*68 + cg*8 + 4];
            ffma2(sa[0], e2, x01.x); ffma2(sa[1], e2, x01.y);
            ffma2(sa[2], e2, x23.x); ffma2(sa[3], e2, x23.y);
        }
        float* Sb = &g_S[b*16384 + hr*512 + ch*64 + cg*8];
        #pragma unroll
        for (int p = 0; p < 4; p++){
            float lo, hi; unpack2f(sa[p], lo, hi);
            atomicAdd(&Sb[2*p], lo);
            atomicAdd(&Sb[2*p+1], hi);
        }
    }
}

// ---------------- T = S @ Win(head cols) + ksum*bin ----------------
__global__ void k_T(const float* __restrict__ Win, const float* __restrict__ bin){
    int blk = blockIdx.x;
    int b = blk >> 3, part = blk & 7;
    int o = part*256 + threadIdx.x;          // [0,2048)
    int hr = o >> 6, d = o & 63, h = hr >> 2;
    const float* Srow = &g_S[b*16384 + hr*512];
    const float* Wcol = &Win[h*64 + d];
    float s = 0.f;
    #pragma unroll 8
    for (int i = 0; i < 512; i++) s += Srow[i] * Wcol[(size_t)i*DX];
    g_T[b*2048 + o] = s + g_ksum[b*32 + hr] * bin[h*64 + d];
}

// ---------------- kv_norm = (T @ Wv) / ksum ----------------
__global__ void k_kv(const float* __restrict__ Wv){
    __shared__ float Ts[2048], Wvs[4096], ks[32];
    int b = blockIdx.x, tid = threadIdx.x;
    for (int i = tid; i < 2048; i += 256) Ts[i] = g_T[b*2048 + i];
    for (int i = tid; i < 4096; i += 256) Wvs[i] = Wv[i];
    if (tid < 32) ks[tid] = g_ksum[b*32 + tid];
    __syncthreads();
    int hr = tid >> 3, cs = tid & 7;
    float acc[8] = {0,0,0,0,0,0,0,0};
    #pragma unroll 4
    for (int d = 0; d < 64; d++){
        float t = Ts[hr*64 + d];
        #pragma unroll
        for (int c = 0; c < 8; c++) acc[c] += t * Wvs[d*64 + cs*8 + c];
    }
    float inv = 1.0f / ks[hr];
    #pragma unroll
    for (int c = 0; c < 8; c++) g_kvn[b*2048 + hr*64 + cs*8 + c] = acc[c] * inv;
}

// ---------------- M2 = kv_norm @ Wout (per-head rows) ----------------
__global__ void k_M2(const float* __restrict__ Wout){
    __shared__ float kvs[2048];
    int b = blockIdx.x >> 2, q4 = blockIdx.x & 3;
    int tid = threadIdx.x;
    for (int i = tid; i < 2048; i += 256) kvs[i] = g_kvn[b*2048 + i];
    __syncthreads();
    int hr = tid >> 3, dg = tid & 7, h = hr >> 2;
    int dout0 = q4*128 + dg*16;
    float acc[16];
    #pragma unroll
    for (int i = 0; i < 16; i++) acc[i] = 0.f;
    #pragma unroll 2
    for (int c = 0; c < 64; c++){
        float kv = kvs[hr*64 + c];
        const float* wrow = &Wout[(size_t)(h*64 + c)*DX + dout0];
        #pragma unroll
        for (int i = 0; i < 16; i++) acc[i] += kv * wrow[i];
    }
    float* dst = &g_M2[b*16384 + hr*512 + dout0];
    #pragma unroll
    for (int i = 0; i < 16; i++) dst[i] = acc[i];
}

// ---------------- output: out = qhat @ M2 + bout ----------------
// smem floats: M2s 16384, qh 128*36=4608, bo 512 -> 21504 (86KB)
#define SM_OUT 21504

__global__ __launch_bounds__(256)
void k_out(const float* __restrict__ bout, float* __restrict__ out){
    extern __shared__ float sm[];
    float* M2s = sm;
    float* qh  = sm + 16384;
    float* bo  = sm + 20992;

    const int tid = threadIdx.x, blk = blockIdx.x;
    const int rg = tid >> 3, cg = tid & 7;
    const int row0 = blk * MT;
    const int b = blk >> 7;

    {
        const float4* src = (const float4*)&g_M2[b*16384];
        for (int i = tid; i < 4096; i += 256) ((float4*)M2s)[i] = src[i];
        const float4* qsrc = (const float4*)&g_q[(size_t)row0*32];
        for (int idx = tid; idx < 1024; idx += 256){
            int r = idx >> 3, c = idx & 7;
            *(float4*)&qh[r*36 + c*4] = qsrc[idx];
        }
        for (int i = tid; i < 512; i += 256) bo[i] = bout[i];
    }
    __syncthreads();

    #pragma unroll 1
    for (int ch4 = 0; ch4 < 4; ch4++){
        const int c0 = ch4*128 + cg*16;
        unsigned long long acc[4][8];
        #pragma unroll
        for (int rr = 0; rr < 4; rr++)
            #pragma unroll
            for (int p = 0; p < 8; p++) acc[rr][p] = 0ull;

        #pragma unroll 2
        for (int j = 0; j < 32; j++){
            ulonglong2 m01 = *(ulonglong2*)&M2s[j*512 + c0];
            ulonglong2 m23 = *(ulonglong2*)&M2s[j*512 + c0 + 4];
            ulonglong2 m45 = *(ulonglong2*)&M2s[j*512 + c0 + 8];
            ulonglong2 m67 = *(ulonglong2*)&M2s[j*512 + c0 + 12];
            #pragma unroll
            for (int rr = 0; rr < 4; rr++){
                float q = qh[(rg*4 + rr)*36 + j];
                unsigned long long a2 = pack2f(q, q);
                ffma2(acc[rr][0], a2, m01.x); ffma2(acc[rr][1], a2, m01.y);
                ffma2(acc[rr][2], a2, m23.x); ffma2(acc[rr][3], a2, m23.y);
                ffma2(acc[rr][4], a2, m45.x); ffma2(acc[rr][5], a2, m45.y);
                ffma2(acc[rr][6], a2, m67.x); ffma2(acc[rr][7], a2, m67.y);
            }
        }
        #pragma unroll
        for (int rr = 0; rr < 4; rr++){
            float o[16];
            #pragma unroll
            for (int p = 0; p < 8; p++) unpack2f(acc[rr][p], o[2*p], o[2*p+1]);
            #pragma unroll
            for (int i = 0; i < 16; i++) o[i] += bo[c0 + i];
            float* dst = &out[(size_t)(row0 + rg*4 + rr)*DX + c0];
            #pragma unroll
            for (int q4 = 0; q4 < 4; q4++){
                float4 v; v.x=o[q4*4]; v.y=o[q4*4+1]; v.z=o[q4*4+2]; v.w=o[q4*4+3];
                *(float4*)&dst[q4*4] = v;
            }
        }
    }
}

// ---------------- launch ----------------
extern "C" void kernel_launch(void* const* d_in, const int* in_sizes, int n_in,
                              void* d_out, int out_size)
{
    const float* x    = (const float*)d_in[0];
    const float* Win  = (const float*)d_in[1];
    const float* bin  = (const float*)d_in[2];
    const float* Wq   = (const float*)d_in[3];
    const float* Wk   = (const float*)d_in[4];
    const float* Wv   = (const float*)d_in[5];
    const float* Wout = (const float*)d_in[6];
    const float* bout = (const float*)d_in[7];
    float* out = (float*)d_out;

    cudaFuncSetAttribute(k_main, cudaFuncAttributeMaxDynamicSharedMemorySize, SM_MAIN*4);
    cudaFuncSetAttribute(k_out,  cudaFuncAttributeMaxDynamicSharedMemorySize, SM_OUT*4);

    k_zero<<<512, 256>>>();
    k_combine<<<129, 256>>>(Win, bin, Wq, Wk);
    k_main<<<GRID_MAIN, 256, SM_MAIN*4>>>(x);
    k_T<<<64, 256>>>(Win, bin);
    k_kv<<<8, 256>>>(Wv);
    k_M2<<<32, 256>>>(Wout);
    k_out<<<GRID_MAIN, 256, SM_OUT*4>>>(bout, out);
}

// round 6
// speedup vs baseline: 25.5199x; 1.0740x over previous
#include <cuda_runtime.h>
#include <math.h>

#define NB    8
#define RTOT  131072
#define DX    512
#define MT    128
#define GRID_MAIN (RTOT/MT)   // 1024

// ---------------- device scratch ----------------
__device__ float g_Wqk[DX*64];
__device__ float g_bqk[64];
__device__ float g_q[(size_t)RTOT*32];   // q-hat [n][h*4+r]
__device__ float g_S[NB*32*DX];          // S_b[hr][i] = sum_n ek*x
__device__ float g_ksum[NB*32];
__device__ float g_T[NB*32*64];
__device__ float g_kvn[NB*32*64];
__device__ float g_M2[NB*32*DX];

// ---------------- packed f32x2 helpers ----------------
__device__ __forceinline__ unsigned long long pack2f(float lo, float hi){
    unsigned long long r; asm("mov.b64 %0,{%1,%2};":"=l"(r):"f"(lo),"f"(hi)); return r;}
__device__ __forceinline__ void unpack2f(unsigned long long v, float&lo, float&hi){
    asm("mov.b64 {%0,%1},%2;":"=f"(lo),"=f"(hi):"l"(v));}
__device__ __forceinline__ void ffma2(unsigned long long&d, unsigned long long a, unsigned long long b){
    asm("fma.rn.f32x2 %0,%1,%2,%0;":"+l"(d):"l"(a),"l"(b));}
__device__ __forceinline__ float f4c(const float4&v,int t){
    return t==0?v.x: t==1?v.y: t==2?v.z: v.w;}

// ---------------- cp.async helpers ----------------
__device__ __forceinline__ unsigned smem_u32(const void* p){
    unsigned r;
    asm("{.reg .u64 t; cvta.to.shared.u64 t,%1; cvt.u32.u64 %0,t;}":"=r"(r):"l"(p));
    return r;
}
__device__ __forceinline__ void cpa16(unsigned s, const void* g){
    asm volatile("cp.async.cg.shared.global [%0],[%1],16;"::"r"(s),"l"(g));
}
#define CPA_COMMIT() asm volatile("cp.async.commit_group;")
#define CPA_WAIT(n)  asm volatile("cp.async.wait_group %0;"::"n"(n))

// ---------------- zero accumulators ----------------
__global__ void k_zero(){
    int i = blockIdx.x*256 + threadIdx.x;
    if (i < NB*32*DX) g_S[i] = 0.0f;
    if (i < NB*32)    g_ksum[i] = 0.0f;
}

// ---------------- fold weights: Wqkc = Win @ blkdiag(Wq|Wk) ----------------
__global__ void k_combine(const float* __restrict__ Win, const float* __restrict__ bin,
                          const float* __restrict__ Wq,  const float* __restrict__ Wk){
    int idx = blockIdx.x*256 + threadIdx.x;
    if (idx < DX*64){
        int i = idx >> 6, j = idx & 63;
        int h = (j >> 2) & 7, r = j & 3;
        const float* W = (j < 32) ? Wq : Wk;
        float s = 0.f;
        #pragma unroll 8
        for (int d = 0; d < 64; d++) s += Win[(size_t)i*DX + h*64 + d] * W[d*4 + r];
        g_Wqk[i*64 + j] = s;
    } else if (idx < DX*64 + 64){
        int j = idx - DX*64;
        int h = (j >> 2) & 7, r = j & 3;
        const float* W = (j < 32) ? Wq : Wk;
        float s = 0.f;
        #pragma unroll 8
        for (int d = 0; d < 64; d++) s += bin[h*64 + d] * W[d*4 + r];
        g_bqk[j] = s;
    }
}

// ---------------- main kernel ----------------
// smem floats: xs0 [0,8704) xs1 [8704,17408) wq [17408,21504) eks [21504,25728)
#define SM_MAIN 25728   // 102912 bytes -> 2 CTAs/SM

__global__ __launch_bounds__(256, 2)
void k_main(const float* __restrict__ x){
    extern __shared__ float sm[];
    float* xs0 = sm;
    float* xs1 = sm + 8704;
    float* wq  = sm + 17408;
    float* eks = sm + 21504;

    const int tid = threadIdx.x, blk = blockIdx.x;
    const int rg = tid >> 3, cg = tid & 7;
    const int row0 = blk * MT;
    const int b = blk >> 7;

    const unsigned xs0a = smem_u32(xs0);
    const unsigned xs1a = smem_u32(xs1);
    // per-thread staging coords: 8 float4 per stage
    const int sr = tid >> 4;          // base row group: rows sr + 16*i
    const int sc = tid & 15;          // float4 col

    // -------- stage helpers (x chunk ch -> buffer) --------
    #define STAGE_X(ch, bufa)                                                   \
        { const float* gsrc = &x[(size_t)row0*DX + (ch)*64 + sc*4];             \
          _Pragma("unroll")                                                     \
          for (int i = 0; i < 8; i++){                                          \
              int r = sr + i*16;                                                \
              cpa16((bufa) + (unsigned)(r*68 + sc*4)*4u,                        \
                    gsrc + (size_t)r*DX);                                       \
          } }

    // wq chunk ldg->regs / sts
    float4 wreg[4];
    #define LDG_WQ(ch)                                                          \
        { _Pragma("unroll")                                                     \
          for (int i = 0; i < 4; i++){                                          \
              int idx = tid + i*256; int k = idx >> 4, c = idx & 15;            \
              wreg[i] = *(const float4*)&g_Wqk[((ch)*64 + k)*64 + c*4];         \
          } }
    #define STS_WQ()                                                            \
        { _Pragma("unroll")                                                     \
          for (int i = 0; i < 4; i++){                                          \
              int idx = tid + i*256; int k = idx >> 4, c = idx & 15;            \
              *(float4*)&wq[k*64 + c*4] = wreg[i];                              \
          } }

    // -------- pass 1: logits = x_tile @ Wqkc (double-buffered) --------
    unsigned long long acc[16];
    #pragma unroll
    for (int p = 0; p < 16; p++) acc[p] = 0ull;

    STAGE_X(0, xs0a); CPA_COMMIT();
    STAGE_X(1, xs1a); CPA_COMMIT();
    LDG_WQ(0); STS_WQ(); LDG_WQ(1);
    CPA_WAIT(1); __syncthreads();

    #pragma unroll 1
    for (int ch = 0; ch < 8; ch++){
        const float* xb = (ch & 1) ? xs1 : xs0;
        #pragma unroll 1
        for (int kk = 0; kk < 64; kk += 4){
            float4 xv[4];
            #pragma unroll
            for (int rr = 0; rr < 4; rr++)
                xv[rr] = *(const float4*)&xb[(rg*4 + rr)*68 + kk];
            #pragma unroll
            for (int t = 0; t < 4; t++){
                ulonglong2 w01 = *(ulonglong2*)&wq[(kk + t)*64 + cg*8];
                ulonglong2 w23 = *(ulonglong2*)&wq[(kk + t)*64 + cg*8 + 4];
                #pragma unroll
                for (int rr = 0; rr < 4; rr++){
                    float a = f4c(xv[rr], t);
                    unsigned long long a2 = pack2f(a, a);
                    ffma2(acc[rr*4+0], a2, w01.x);
                    ffma2(acc[rr*4+1], a2, w01.y);
                    ffma2(acc[rr*4+2], a2, w23.x);
                    ffma2(acc[rr*4+3], a2, w23.y);
                }
            }
        }
        __syncthreads();
        if (ch < 7){
            STS_WQ();                            // wq(ch+1) -> smem
            if (ch < 6){
                LDG_WQ(ch+2);
                unsigned dst = (ch & 1) ? xs1a : xs0a;
                STAGE_X(ch+2, dst); CPA_COMMIT();
                CPA_WAIT(1);
            } else {
                CPA_WAIT(0);
            }
            __syncthreads();
        }
    }

    // -------- pass 2: q softmax -> g_q ; exp(k) -> eks --------
    float bj[8];
    #pragma unroll
    for (int o = 0; o < 8; o++) bj[o] = g_bqk[cg*8 + o];

    #pragma unroll
    for (int rr = 0; rr < 4; rr++){
        float v[8];
        #pragma unroll
        for (int p = 0; p < 4; p++) unpack2f(acc[rr*4 + p], v[2*p], v[2*p+1]);
        #pragma unroll
        for (int o = 0; o < 8; o++) v[o] += bj[o];

        int lrow = rg*4 + rr;
        if (cg < 4){
            size_t n = (size_t)row0 + lrow;
            #pragma unroll
            for (int hh = 0; hh < 2; hh++){
                float* p = v + hh*4;
                float m = fmaxf(fmaxf(p[0], p[1]), fmaxf(p[2], p[3]));
                float e0 = expf(p[0]-m), e1 = expf(p[1]-m);
                float e2 = expf(p[2]-m), e3 = expf(p[3]-m);
                float inv = 1.0f/(e0+e1+e2+e3);
                float4 qv; qv.x=e0*inv; qv.y=e1*inv; qv.z=e2*inv; qv.w=e3*inv;
                *(float4*)&g_q[n*32 + cg*8 + hh*4] = qv;
            }
        } else {
            #pragma unroll
            for (int o = 0; o < 8; o++)
                eks[lrow*33 + (cg-4)*8 + o] = expf(v[o]);
        }
    }

    // -------- pass 3: S += eks^T @ x (double-buffered restage) --------
    STAGE_X(0, xs0a); CPA_COMMIT();
    STAGE_X(1, xs1a); CPA_COMMIT();
    CPA_WAIT(1); __syncthreads();   // also publishes eks

    // ksum partials (eks visible after the sync above)
    if (tid < 32){
        float s = 0.f;
        #pragma unroll 8
        for (int r = 0; r < 128; r++) s += eks[r*33 + tid];
        atomicAdd(&g_ksum[b*32 + tid], s);
    }

    #pragma unroll 1
    for (int ch = 0; ch < 8; ch++){
        const float* xb = (ch & 1) ? xs1 : xs0;
        const int hr = rg;
        unsigned long long sa[4];
        #pragma unroll
        for (int p = 0; p < 4; p++) sa[p] = 0ull;
        #pragma unroll 4
        for (int row = 0; row < 128; row++){
            float e = eks[row*33 + hr];
            unsigned long long e2 = pack2f(e, e);
            ulonglong2 x01 = *(const ulonglong2*)&xb[row*68 + cg*8];
            ulonglong2 x23 = *(const ulonglong2*)&xb[row*68 + cg*8 + 4];
            ffma2(sa[0], e2, x01.x); ffma2(sa[1], e2, x01.y);
            ffma2(sa[2], e2, x23.x); ffma2(sa[3], e2, x23.y);
        }
        float* Sb = &g_S[b*16384 + hr*512 + ch*64 + cg*8];
        #pragma unroll
        for (int p = 0; p < 4; p++){
            float lo, hi; unpack2f(sa[p], lo, hi);
            atomicAdd(&Sb[2*p], lo);
            atomicAdd(&Sb[2*p+1], hi);
        }
        if (ch < 7){
            __syncthreads();                     // everyone done with xb
            if (ch < 6){
                unsigned dst = (ch & 1) ? xs1a : xs0a;
                STAGE_X(ch+2, dst); CPA_COMMIT();
                CPA_WAIT(1);
            } else {
                CPA_WAIT(0);
            }
            __syncthreads();
        }
    }
    #undef STAGE_X
    #undef LDG_WQ
    #undef STS_WQ
}

// ---------------- T = S @ Win(head cols) + ksum*bin  (coalesced) ----------------
__global__ void k_T(const float* __restrict__ Win, const float* __restrict__ bin){
    __shared__ float Ss[4*512];
    const int b = blockIdx.x >> 3, h = blockIdx.x & 7;
    const int tid = threadIdx.x;
    for (int i = tid; i < 2048; i += 256)
        Ss[i] = g_S[b*16384 + (h*4)*512 + i];
    __syncthreads();
    const int r = tid >> 6, d = tid & 63;
    const float* W = &Win[h*64 + d];
    const float* Sr = &Ss[r*512];
    float s = 0.f;
    #pragma unroll 8
    for (int i = 0; i < 512; i++) s += Sr[i] * W[(size_t)i*DX];
    g_T[b*2048 + (h*4 + r)*64 + d] = s + g_ksum[b*32 + h*4 + r] * bin[h*64 + d];
}

// ---------------- kv_norm = (T @ Wv) / ksum ----------------
__global__ void k_kv(const float* __restrict__ Wv){
    __shared__ float Ts[2048], Wvs[4096], ks[32];
    int b = blockIdx.x, tid = threadIdx.x;
    for (int i = tid; i < 2048; i += 256) Ts[i] = g_T[b*2048 + i];
    for (int i = tid; i < 4096; i += 256) Wvs[i] = Wv[i];
    if (tid < 32) ks[tid] = g_ksum[b*32 + tid];
    __syncthreads();
    int hr = tid >> 3, cs = tid & 7;
    float acc[8] = {0,0,0,0,0,0,0,0};
    #pragma unroll 4
    for (int d = 0; d < 64; d++){
        float t = Ts[hr*64 + d];
        #pragma unroll
        for (int c = 0; c < 8; c++) acc[c] += t * Wvs[d*64 + cs*8 + c];
    }
    float inv = 1.0f / ks[hr];
    #pragma unroll
    for (int c = 0; c < 8; c++) g_kvn[b*2048 + hr*64 + cs*8 + c] = acc[c] * inv;
}

// ---------------- M2 = kv_norm @ Wout ----------------
__global__ void k_M2(const float* __restrict__ Wout){
    __shared__ float kvs[2048];
    int b = blockIdx.x >> 2, q4 = blockIdx.x & 3;
    int tid = threadIdx.x;
    for (int i = tid; i < 2048; i += 256) kvs[i] = g_kvn[b*2048 + i];
    __syncthreads();
    int hr = tid >> 3, dg = tid & 7, h = hr >> 2;
    int dout0 = q4*128 + dg*16;
    float acc[16];
    #pragma unroll
    for (int i = 0; i < 16; i++) acc[i] = 0.f;
    #pragma unroll 2
    for (int c = 0; c < 64; c++){
        float kv = kvs[hr*64 + c];
        const float* wrow = &Wout[(size_t)(h*64 + c)*DX + dout0];
        #pragma unroll
        for (int i = 0; i < 16; i++) acc[i] += kv * wrow[i];
    }
    float* dst = &g_M2[b*16384 + hr*512 + dout0];
    #pragma unroll
    for (int i = 0; i < 16; i++) dst[i] = acc[i];
}

// ---------------- output: out = qhat @ M2 + bout ----------------
#define SM_OUT 21504

__global__ __launch_bounds__(256)
void k_out(const float* __restrict__ bout, float* __restrict__ out){
    extern __shared__ float sm[];
    float* M2s = sm;
    float* qh  = sm + 16384;
    float* bo  = sm + 20992;

    const int tid = threadIdx.x, blk = blockIdx.x;
    const int rg = tid >> 3, cg = tid & 7;
    const int row0 = blk * MT;
    const int b = blk >> 7;

    {
        const float4* src = (const float4*)&g_M2[b*16384];
        for (int i = tid; i < 4096; i += 256) ((float4*)M2s)[i] = src[i];
        const float4* qsrc = (const float4*)&g_q[(size_t)row0*32];
        for (int idx = tid; idx < 1024; idx += 256){
            int r = idx >> 3, c = idx & 7;
            *(float4*)&qh[r*36 + c*4] = qsrc[idx];
        }
        for (int i = tid; i < 512; i += 256) bo[i] = bout[i];
    }
    __syncthreads();

    #pragma unroll 1
    for (int ch4 = 0; ch4 < 4; ch4++){
        const int c0 = ch4*128 + cg*16;
        unsigned long long acc[4][8];
        #pragma unroll
        for (int rr = 0; rr < 4; rr++)
            #pragma unroll
            for (int p = 0; p < 8; p++) acc[rr][p] = 0ull;

        #pragma unroll 2
        for (int j = 0; j < 32; j++){
            ulonglong2 m01 = *(ulonglong2*)&M2s[j*512 + c0];
            ulonglong2 m23 = *(ulonglong2*)&M2s[j*512 + c0 + 4];
            ulonglong2 m45 = *(ulonglong2*)&M2s[j*512 + c0 + 8];
            ulonglong2 m67 = *(ulonglong2*)&M2s[j*512 + c0 + 12];
            #pragma unroll
            for (int rr = 0; rr < 4; rr++){
                float q = qh[(rg*4 + rr)*36 + j];
                unsigned long long a2 = pack2f(q, q);
                ffma2(acc[rr][0], a2, m01.x); ffma2(acc[rr][1], a2, m01.y);
                ffma2(acc[rr][2], a2, m23.x); ffma2(acc[rr][3], a2, m23.y);
                ffma2(acc[rr][4], a2, m45.x); ffma2(acc[rr][5], a2, m45.y);
                ffma2(acc[rr][6], a2, m67.x); ffma2(acc[rr][7], a2, m67.y);
            }
        }
        #pragma unroll
        for (int rr = 0; rr < 4; rr++){
            float o[16];
            #pragma unroll
            for (int p = 0; p < 8; p++) unpack2f(acc[rr][p], o[2*p], o[2*p+1]);
            #pragma unroll
            for (int i = 0; i < 16; i++) o[i] += bo[c0 + i];
            float* dst = &out[(size_t)(row0 + rg*4 + rr)*DX + c0];
            #pragma unroll
            for (int q4 = 0; q4 < 4; q4++){
                float4 v; v.x=o[q4*4]; v.y=o[q4*4+1]; v.z=o[q4*4+2]; v.w=o[q4*4+3];
                *(float4*)&dst[q4*4] = v;
            }
        }
    }
}

// ---------------- launch ----------------
extern "C" void kernel_launch(void* const* d_in, const int* in_sizes, int n_in,
                              void* d_out, int out_size)
{
    const float* x    = (const float*)d_in[0];
    const float* Win  = (const float*)d_in[1];
    const float* bin  = (const float*)d_in[2];
    const float* Wq   = (const float*)d_in[3];
    const float* Wk   = (const float*)d_in[4];
    const float* Wv   = (const float*)d_in[5];
    const float* Wout = (const float*)d_in[6];
    const float* bout = (const float*)d_in[7];
    float* out = (float*)d_out;

    cudaFuncSetAttribute(k_main, cudaFuncAttributeMaxDynamicSharedMemorySize, SM_MAIN*4);
    cudaFuncSetAttribute(k_out,  cudaFuncAttributeMaxDynamicSharedMemorySize, SM_OUT*4);

    k_zero<<<512, 256>>>();
    k_combine<<<129, 256>>>(Win, bin, Wq, Wk);
    k_main<<<GRID_MAIN, 256, SM_MAIN*4>>>(x);
    k_T<<<64, 256>>>(Win, bin);
    k_kv<<<8, 256>>>(Wv);
    k_M2<<<32, 256>>>(Wout);
    k_out<<<GRID_MAIN, 256, SM_OUT*4>>>(bout, out);
}

// round 11
// speedup vs baseline: 35.2121x; 1.3798x over previous
#include <cuda_runtime.h>
#include <cuda_bf16.h>
#include <mma.h>
#include <math.h>
#include <stdint.h>

using namespace nvcuda;

#define NB    8
#define RTOT  131072
#define DX    512
#define MT    128
#define GRID_MAIN (RTOT/MT)   // 1024

// ---------------- device scratch ----------------
__device__ float g_q[(size_t)RTOT*32];       // q-hat fp32
__device__ float g_S[NB*32*DX];
__device__ float g_ksum[NB*32];
__device__ float g_T[NB*2048];
__device__ float g_kvn[NB*2048];
__device__ float g_bqk[64];
__device__ unsigned short g_B1h[8*4096];     // pass1 B chunks [ch][64k][64n] bf16 hi
__device__ unsigned short g_B1l[8*4096];
__device__ unsigned short g_Boh[NB*48*512];  // k_out B [b][48k][512n] bf16 hi (row32=bout, 33..47=0)
__device__ unsigned short g_Bol[NB*48*512];

// ---------------- helpers ----------------
__device__ __forceinline__ unsigned long long pack2f(float lo, float hi){
    unsigned long long r; asm("mov.b64 %0,{%1,%2};":"=l"(r):"f"(lo),"f"(hi)); return r;}
__device__ __forceinline__ void unpack2f(unsigned long long v, float&lo, float&hi){
    asm("mov.b64 {%0,%1},%2;":"=f"(lo),"=f"(hi):"l"(v));}
__device__ __forceinline__ void ffma2(unsigned long long&d, unsigned long long a, unsigned long long b){
    asm("fma.rn.f32x2 %0,%1,%2,%0;":"+l"(d):"l"(a),"l"(b));}

__device__ __forceinline__ unsigned smem_u32(const void* p){
    unsigned r;
    asm("{.reg .u64 t; cvta.to.shared.u64 t,%1; cvt.u32.u64 %0,t;}":"=r"(r):"l"(p));
    return r;
}
__device__ __forceinline__ void cpa16(unsigned s, const void* g){
    asm volatile("cp.async.cg.shared.global [%0],[%1],16;"::"r"(s),"l"(g));
}
#define CPA_COMMIT() asm volatile("cp.async.commit_group;")
#define CPA_WAIT0()  asm volatile("cp.async.wait_group 0;")

// bf16 round-to-nearest split
__device__ __forceinline__ void bf16split(float f, uint32_t& hb, uint32_t& lb){
    uint32_t u = __float_as_uint(f);
    hb = (u + 0x7FFFu + ((u >> 16) & 1u)) >> 16;
    float hf = __uint_as_float(hb << 16);
    uint32_t lu = __float_as_uint(f - hf);
    lb = (lu + 0x7FFFu + ((lu >> 16) & 1u)) >> 16;
}

// ---------------- zero accumulators + static rows of k_out B ----------------
__global__ void k_zero(const float* __restrict__ bout){
    int i = blockIdx.x*256 + threadIdx.x;       // grid 512*256 = 131072
    if (i < NB*32*DX) g_S[i] = 0.0f;
    if (i < NB*2048)  g_T[i] = 0.0f;
    if (i < NB*32)    g_ksum[i] = 0.0f;
    if (i < NB*16*512){                          // rows 32..47 of k_out B
        int b = i >> 13, rem = i & 8191;
        int k = 32 + (rem >> 9), d = rem & 511;
        unsigned short vh = 0, vl = 0;
        if (k == 32){
            uint32_t hb, lb; bf16split(bout[d], hb, lb);
            vh = (unsigned short)hb; vl = (unsigned short)lb;
        }
        g_Boh[((size_t)b*48 + k)*512 + d] = vh;
        g_Bol[((size_t)b*48 + k)*512 + d] = vl;
    }
}

// ---------------- fold weights -> bf16 hi/lo B chunks + bias ----------------
__global__ void k_combine(const float* __restrict__ Win, const float* __restrict__ bin,
                          const float* __restrict__ Wq,  const float* __restrict__ Wk){
    int idx = blockIdx.x*256 + threadIdx.x;
    if (idx < DX*64){
        int i = idx >> 6, j = idx & 63;          // i: K, j: col
        int h = (j >> 2) & 7, r = j & 3;
        const float* W = (j < 32) ? Wq : Wk;
        float s = 0.f;
        #pragma unroll 8
        for (int d = 0; d < 64; d++) s += Win[(size_t)i*DX + h*64 + d] * W[d*4 + r];
        uint32_t hb, lb; bf16split(s, hb, lb);
        int ch = i >> 6;
        int off = ch*4096 + (i & 63)*64 + j;     // [ch][k][n] row-major
        g_B1h[off] = (unsigned short)hb;
        g_B1l[off] = (unsigned short)lb;
    } else if (idx < DX*64 + 64){
        int j = idx - DX*64;
        int h = (j >> 2) & 7, r = j & 3;
        const float* W = (j < 32) ? Wq : Wk;
        float s = 0.f;
        #pragma unroll 8
        for (int d = 0; d < 64; d++) s += bin[h*64 + d] * W[d*4 + r];
        g_bqk[j] = s;
    }
}

// ---------------- main kernel: wmma logits + softmax/exp + scalar S accum ----
// bytes: pass1 AH[0,18432) AL[18432,36864) BH[36864,46080) BL[46080,55296)
//        C (fp32 [128][72]) reuses [0,36864)
//        pass3 xs0[0,34816) xs1[34816,69632)
//        eks [69632,86528)  bqs [86528,86784)
#define SM_MAIN 86784

__global__ __launch_bounds__(256, 2)
void k_main(const float* __restrict__ x){
    extern __shared__ __align__(1024) unsigned char smraw[];
    const uint32_t sbase = smem_u32(smraw);
    const uint32_t AH = 0, AL = 18432, BH = 36864, BL = 46080;
    float* xs0 = (float*)(smraw);
    float* xs1 = (float*)(smraw + 34816);
    float* eks = (float*)(smraw + 69632);
    float* bqs = (float*)(smraw + 86528);
    float* Cs  = (float*)(smraw);

    const int tid = threadIdx.x, wid = tid >> 5;
    const int blk = blockIdx.x, row0 = blk * MT, b = blk >> 7;

    if (tid < 64) bqs[tid] = g_bqk[tid];

    // ============ pass 1: logits[128x64] = x @ Wqkc via wmma bf16 ============
    float4 xr[8];
    #define LDGX(ch) { _Pragma("unroll") for (int i = 0; i < 8; i++){ \
        int idx = tid + i*256; int r = idx >> 4, c = idx & 15; \
        xr[i] = *(const float4*)&x[(size_t)(row0 + r)*DX + (ch)*64 + c*4]; } }

    wmma::fragment<wmma::accumulator,16,16,16,float> acc[4];
    #pragma unroll
    for (int nt = 0; nt < 4; nt++) wmma::fill_fragment(acc[nt], 0.0f);

    LDGX(0);
    #pragma unroll 1
    for (int ch = 0; ch < 8; ch++){
        if (ch) __syncthreads();   // previous chunk compute finished
        // convert x regs -> bf16 hi/lo A tiles (row-major, ldm 72)
        #pragma unroll
        for (int i = 0; i < 8; i++){
            int idx = tid + i*256; int r = idx >> 4, c = idx & 15;
            float f[4] = {xr[i].x, xr[i].y, xr[i].z, xr[i].w};
            uint32_t hb[4], lb[4];
            #pragma unroll
            for (int t = 0; t < 4; t++) bf16split(f[t], hb[t], lb[t]);
            uint2 hp = make_uint2(hb[0] | (hb[1] << 16), hb[2] | (hb[3] << 16));
            uint2 lp = make_uint2(lb[0] | (lb[1] << 16), lb[2] | (lb[3] << 16));
            uint32_t off = (uint32_t)(r*72 + c*4)*2u;
            *(uint2*)(smraw + AH + off) = hp;
            *(uint2*)(smraw + AL + off) = lp;
        }
        // stage B chunk [64k][64n] -> smem [64][72] hi/lo via cp.async
        {
            const unsigned short* gh = g_B1h + ch*4096;
            const unsigned short* gl = g_B1l + ch*4096;
            #pragma unroll
            for (int i = 0; i < 2; i++){
                int idx = tid + i*256;            // 512 groups of 8 bf16
                int k = idx >> 3, c8 = idx & 7;
                uint32_t doff = (uint32_t)(k*72 + c8*8)*2u;
                cpa16(sbase + BH + doff, gh + k*64 + c8*8);
                cpa16(sbase + BL + doff, gl + k*64 + c8*8);
            }
            CPA_COMMIT();
        }
        if (ch < 7) LDGX(ch + 1);
        CPA_WAIT0();
        __syncthreads();

        // compute: warp w owns rows w*16..w*16+15
        const __nv_bfloat16* Ahp = (const __nv_bfloat16*)(smraw + AH) + wid*16*72;
        const __nv_bfloat16* Alp = (const __nv_bfloat16*)(smraw + AL) + wid*16*72;
        const __nv_bfloat16* Bhp = (const __nv_bfloat16*)(smraw + BH);
        const __nv_bfloat16* Blp = (const __nv_bfloat16*)(smraw + BL);
        #pragma unroll
        for (int ks = 0; ks < 4; ks++){
            wmma::fragment<wmma::matrix_a,16,16,16,__nv_bfloat16,wmma::row_major> ah, al;
            wmma::load_matrix_sync(ah, Ahp + ks*16, 72);
            wmma::load_matrix_sync(al, Alp + ks*16, 72);
            #pragma unroll
            for (int nt = 0; nt < 4; nt++){
                wmma::fragment<wmma::matrix_b,16,16,16,__nv_bfloat16,wmma::row_major> bh, bl;
                wmma::load_matrix_sync(bh, Bhp + ks*16*72 + nt*16, 72);
                wmma::load_matrix_sync(bl, Blp + ks*16*72 + nt*16, 72);
                wmma::mma_sync(acc[nt], ah, bh, acc[nt]);
                wmma::mma_sync(acc[nt], ah, bl, acc[nt]);
                wmma::mma_sync(acc[nt], al, bh, acc[nt]);
            }
        }
    }
    #undef LDGX
    __syncthreads();
    // store logits to smem C [128][72] fp32
    #pragma unroll
    for (int nt = 0; nt < 4; nt++)
        wmma::store_matrix_sync(Cs + wid*16*72 + nt*16, acc[nt], 72, wmma::mem_row_major);
    __syncthreads();

    // ============ epilogue: softmax(q) -> g_q ; exp(k) -> eks ============
    if (tid < 128){
        const int r = tid;
        const float* crow = Cs + r*72;
        size_t n = (size_t)row0 + r;
        #pragma unroll
        for (int h = 0; h < 8; h++){
            float v0 = crow[h*4+0] + bqs[h*4+0];
            float v1 = crow[h*4+1] + bqs[h*4+1];
            float v2 = crow[h*4+2] + bqs[h*4+2];
            float v3 = crow[h*4+3] + bqs[h*4+3];
            float m = fmaxf(fmaxf(v0, v1), fmaxf(v2, v3));
            float e0 = expf(v0-m), e1 = expf(v1-m), e2 = expf(v2-m), e3 = expf(v3-m);
            float inv = 1.0f/(e0+e1+e2+e3);
            float4 qv; qv.x = e0*inv; qv.y = e1*inv; qv.z = e2*inv; qv.w = e3*inv;
            *(float4*)&g_q[n*32 + h*4] = qv;
        }
        float ek[32];
        #pragma unroll
        for (int j = 0; j < 32; j++) ek[j] = expf(crow[32 + j] + bqs[32 + j]);
        #pragma unroll
        for (int j = 0; j < 32; j++) eks[r*33 + j] = ek[j];
    }
    __syncthreads();

    // ksum partials
    if (tid < 32){
        float s = 0.f;
        #pragma unroll 8
        for (int r = 0; r < 128; r++) s += eks[r*33 + tid];
        atomicAdd(&g_ksum[b*32 + tid], s);
    }

    // ============ pass 3: S += eks^T @ x (scalar fp32, cp.async pipelined) ====
    const uint32_t xs0a = smem_u32(xs0), xs1a = smem_u32(xs1);
    const int sr = tid >> 4, sc = tid & 15;
    const int rg = tid >> 3, cg = tid & 7;
    #define STAGE_X(ch, bufa) { const float* gsrc = &x[(size_t)row0*DX + (ch)*64 + sc*4]; \
        _Pragma("unroll") for (int i = 0; i < 8; i++){ int r = sr + i*16; \
            cpa16((bufa) + (unsigned)(r*68 + sc*4)*4u, gsrc + (size_t)r*DX); } }

    STAGE_X(0, xs0a); CPA_COMMIT();
    STAGE_X(1, xs1a); CPA_COMMIT();
    asm volatile("cp.async.wait_group 1;");
    __syncthreads();

    #pragma unroll 1
    for (int ch = 0; ch < 8; ch++){
        const float* xb = (ch & 1) ? xs1 : xs0;
        const int hr = rg;
        unsigned long long sa[4];
        #pragma unroll
        for (int p = 0; p < 4; p++) sa[p] = 0ull;
        #pragma unroll 4
        for (int row = 0; row < 128; row++){
            float e = eks[row*33 + hr];
            unsigned long long e2 = pack2f(e, e);
            ulonglong2 x01 = *(const ulonglong2*)&xb[row*68 + cg*8];
            ulonglong2 x23 = *(const ulonglong2*)&xb[row*68 + cg*8 + 4];
            ffma2(sa[0], e2, x01.x); ffma2(sa[1], e2, x01.y);
            ffma2(sa[2], e2, x23.x); ffma2(sa[3], e2, x23.y);
        }
        float* Sb = &g_S[b*16384 + hr*512 + ch*64 + cg*8];
        #pragma unroll
        for (int p = 0; p < 4; p++){
            float lo, hi; unpack2f(sa[p], lo, hi);
            atomicAdd(&Sb[2*p], lo);
            atomicAdd(&Sb[2*p+1], hi);
        }
        if (ch < 7){
            __syncthreads();
            if (ch < 6){
                unsigned dst = (ch & 1) ? xs1a : xs0a;
                STAGE_X(ch+2, dst); CPA_COMMIT();
                asm volatile("cp.async.wait_group 1;");
            } else {
                CPA_WAIT0();
            }
            __syncthreads();
        }
    }
    #undef STAGE_X
}

// ---------------- T += S @ Win(head cols), split-K x4 ----------------
__global__ void k_T(const float* __restrict__ Win){
    __shared__ float Ss[4*128];
    const int bh = blockIdx.x >> 2, ks = blockIdx.x & 3;
    const int b = bh >> 3, h = bh & 7;
    const int tid = threadIdx.x;
    const int i0 = ks * 128;
    for (int idx = tid; idx < 512; idx += 256){
        int r = idx >> 7, i = idx & 127;
        Ss[r*128 + i] = g_S[b*16384 + (h*4 + r)*512 + i0 + i];
    }
    __syncthreads();
    const int r = tid >> 6, d = tid & 63;
    const float* W = &Win[(size_t)i0*DX + h*64 + d];
    float s = 0.f;
    #pragma unroll 16
    for (int i = 0; i < 128; i++) s += Ss[r*128 + i] * W[(size_t)i*DX];
    atomicAdd(&g_T[b*2048 + (h*4 + r)*64 + d], s);
}

// ---------------- kv_norm = ((T + ksum*bin) @ Wv) / ksum ----------------
__global__ void k_kv(const float* __restrict__ Wv, const float* __restrict__ bin){
    __shared__ float Ts[2048], Wvs[4096], ks[32];
    int b = blockIdx.x, tid = threadIdx.x;
    if (tid < 32) ks[tid] = g_ksum[b*32 + tid];
    for (int i = tid; i < 4096; i += 256) Wvs[i] = Wv[i];
    __syncthreads();
    for (int i = tid; i < 2048; i += 256)
        Ts[i] = g_T[b*2048 + i] + ks[i >> 6] * bin[(i >> 8)*64 + (i & 63)];
    __syncthreads();
    int hr = tid >> 3, cs = tid & 7;
    float acc[8] = {0,0,0,0,0,0,0,0};
    #pragma unroll 4
    for (int d = 0; d < 64; d++){
        float t = Ts[hr*64 + d];
        #pragma unroll
        for (int c = 0; c < 8; c++) acc[c] += t * Wvs[d*64 + cs*8 + c];
    }
    float inv = 1.0f / ks[hr];
    #pragma unroll
    for (int c = 0; c < 8; c++) g_kvn[b*2048 + hr*64 + cs*8 + c] = acc[c] * inv;
}

// ---------------- M2 = kv_norm @ Wout -> bf16 hi/lo rows 0..31 of k_out B ----
__global__ void k_M2(const float* __restrict__ Wout){
    __shared__ float kvs[2048];
    int b = blockIdx.x >> 2, q4 = blockIdx.x & 3;
    int tid = threadIdx.x;
    for (int i = tid; i < 2048; i += 256) kvs[i] = g_kvn[b*2048 + i];
    __syncthreads();
    int hr = tid >> 3, dg = tid & 7, h = hr >> 2;
    int dout0 = q4*128 + dg*16;
    float acc[16];
    #pragma unroll
    for (int i = 0; i < 16; i++) acc[i] = 0.f;
    #pragma unroll 2
    for (int c = 0; c < 64; c++){
        float kv = kvs[hr*64 + c];
        const float* wrow = &Wout[(size_t)(h*64 + c)*DX + dout0];
        #pragma unroll
        for (int i = 0; i < 16; i++) acc[i] += kv * wrow[i];
    }
    size_t base = ((size_t)b*48 + hr)*512 + dout0;   // B row = hr (K index)
    #pragma unroll
    for (int i = 0; i < 16; i++){
        uint32_t hb, lb; bf16split(acc[i], hb, lb);
        g_Boh[base + i] = (unsigned short)hb;
        g_Bol[base + i] = (unsigned short)lb;
    }
}

// ---------------- output: out = [qhat|1] @ [M2;bout] via wmma (bias in K) ----
// bytes: AH[0,14336) AL[14336,28672) BH[28672,78592) BL[78592,128512)
#define SM_OUT 128512

__global__ __launch_bounds__(256)
void k_out(float* __restrict__ out){
    extern __shared__ __align__(1024) unsigned char smraw[];
    const uint32_t sbase = smem_u32(smraw);
    const uint32_t AH = 0, AL = 14336, BH = 28672, BL = 78592;

    const int tid = threadIdx.x, wid = tid >> 5;
    const int blk = blockIdx.x, row0 = blk * MT, b = blk >> 7;

    // stage B [48][512] -> smem [48][520] hi/lo
    {
        const unsigned short* gh = g_Boh + (size_t)b*48*512;
        const unsigned short* gl = g_Bol + (size_t)b*48*512;
        #pragma unroll
        for (int i = 0; i < 12; i++){
            int idx = tid + i*256;               // 3072 groups of 8 bf16
            int k = idx >> 6, c8 = idx & 63;
            uint32_t doff = (uint32_t)(k*520 + c8*8)*2u;
            cpa16(sbase + BH + doff, gh + k*512 + c8*8);
            cpa16(sbase + BL + doff, gl + k*512 + c8*8);
        }
        CPA_COMMIT();
    }
    // build A [128][56]: cols 0..31 = qhat split, col 32 = 1, 33..55 = 0
    #pragma unroll
    for (int i = 0; i < 4; i++){
        int idx = tid + i*256; int r = idx >> 3, c = idx & 7;
        float4 q = *(const float4*)&g_q[((size_t)row0 + r)*32 + c*4];
        float f[4] = {q.x, q.y, q.z, q.w};
        uint32_t hb[4], lb[4];
        #pragma unroll
        for (int t = 0; t < 4; t++) bf16split(f[t], hb[t], lb[t]);
        uint2 hp = make_uint2(hb[0] | (hb[1] << 16), hb[2] | (hb[3] << 16));
        uint2 lp = make_uint2(lb[0] | (lb[1] << 16), lb[2] | (lb[3] << 16));
        uint32_t off = (uint32_t)(r*56 + c*4)*2u;
        *(uint2*)(smraw + AH + off) = hp;
        *(uint2*)(smraw + AL + off) = lp;
    }
    #pragma unroll
    for (int i = 0; i < 6; i++){
        int idx = tid + i*256;                    // 1536 uint32: cols 32..55
        int r = idx / 12, c2 = idx % 12;
        uint32_t off = (uint32_t)(r*56 + 32 + c2*2)*2u;
        *(uint32_t*)(smraw + AH + off) = (c2 == 0) ? 0x00003F80u : 0u;  // bf16(1.0)
        *(uint32_t*)(smraw + AL + off) = 0u;
    }
    CPA_WAIT0();
    __syncthreads();

    const __nv_bfloat16* Ahp = (const __nv_bfloat16*)(smraw + AH) + wid*16*56;
    const __nv_bfloat16* Alp = (const __nv_bfloat16*)(smraw + AL) + wid*16*56;
    const __nv_bfloat16* Bhp = (const __nv_bfloat16*)(smraw + BH);
    const __nv_bfloat16* Blp = (const __nv_bfloat16*)(smraw + BL);

    #pragma unroll 1
    for (int npass = 0; npass < 4; npass++){
        wmma::fragment<wmma::accumulator,16,16,16,float> acc[8];
        #pragma unroll
        for (int nt = 0; nt < 8; nt++) wmma::fill_fragment(acc[nt], 0.0f);
        #pragma unroll
        for (int ks = 0; ks < 3; ks++){
            wmma::fragment<wmma::matrix_a,16,16,16,__nv_bfloat16,wmma::row_major> ah, al;
            wmma::load_matrix_sync(ah, Ahp + ks*16, 56);
            wmma::load_matrix_sync(al, Alp + ks*16, 56);
            #pragma unroll
            for (int nt = 0; nt < 8; nt++){
                int n0 = npass*128 + nt*16;
                wmma::fragment<wmma::matrix_b,16,16,16,__nv_bfloat16,wmma::row_major> bh, bl;
                wmma::load_matrix_sync(bh, Bhp + ks*16*520 + n0, 520);
                wmma::load_matrix_sync(bl, Blp + ks*16*520 + n0, 520);
                wmma::mma_sync(acc[nt], ah, bh, acc[nt]);
                wmma::mma_sync(acc[nt], ah, bl, acc[nt]);
                wmma::mma_sync(acc[nt], al, bh, acc[nt]);
            }
        }
        float* orow = out + ((size_t)row0 + wid*16)*DX + npass*128;
        #pragma unroll
        for (int nt = 0; nt < 8; nt++)
            wmma::store_matrix_sync(orow + nt*16, acc[nt], DX, wmma::mem_row_major);
    }
}

// ---------------- launch ----------------
extern "C" void kernel_launch(void* const* d_in, const int* in_sizes, int n_in,
                              void* d_out, int out_size)
{
    const float* x    = (const float*)d_in[0];
    const float* Win  = (const float*)d_in[1];
    const float* bin  = (const float*)d_in[2];
    const float* Wq   = (const float*)d_in[3];
    const float* Wk   = (const float*)d_in[4];
    const float* Wv   = (const float*)d_in[5];
    const float* Wout = (const float*)d_in[6];
    const float* bout = (const float*)d_in[7];
    float* out = (float*)d_out;

    cudaFuncSetAttribute(k_main, cudaFuncAttributeMaxDynamicSharedMemorySize, SM_MAIN);
    cudaFuncSetAttribute(k_out,  cudaFuncAttributeMaxDynamicSharedMemorySize, SM_OUT);

    k_zero<<<512, 256>>>(bout);
    k_combine<<<129, 256>>>(Win, bin, Wq, Wk);
    k_main<<<GRID_MAIN, 256, SM_MAIN>>>(x);
    k_T<<<256, 256>>>(Win);
    k_kv<<<8, 256>>>(Wv, bin);
    k_M2<<<32, 256>>>(Wout);
    k_out<<<GRID_MAIN, 256, SM_OUT>>>(out);
}

// round 15
// speedup vs baseline: 64.3716x; 1.8281x over previous
#include <cuda_runtime.h>
#include <cuda_bf16.h>
#include <mma.h>
#include <math.h>
#include <stdint.h>

using namespace nvcuda;

#define NB    8
#define RTOT  131072
#define DX    512
#define MT    128
#define GRID_MAIN (RTOT/MT)   // 1024

// ---------------- device scratch ----------------
__device__ float g_q[(size_t)RTOT*32];       // q-hat fp32
__device__ float g_S[NB*32*DX];
__device__ float g_ksum[NB*32];
__device__ float g_T[NB*2048];
__device__ float g_kvn[NB*2048];
__device__ float g_bqk[64];
__device__ unsigned short g_B1h[8*4096];     // pass1 B chunks [ch][64k][64n] bf16 hi
__device__ unsigned short g_B1l[8*4096];
__device__ unsigned short g_Boh[NB*48*512];  // k_out B [b][48k][512n] bf16 hi (row32=bout, 33..47=0)
__device__ unsigned short g_Bol[NB*48*512];

// ---------------- helpers ----------------
__device__ __forceinline__ unsigned smem_u32(const void* p){
    unsigned r;
    asm("{.reg .u64 t; cvta.to.shared.u64 t,%1; cvt.u32.u64 %0,t;}":"=r"(r):"l"(p));
    return r;
}
__device__ __forceinline__ void cpa16(unsigned s, const void* g){
    asm volatile("cp.async.cg.shared.global [%0],[%1],16;"::"r"(s),"l"(g));
}
#define CPA_COMMIT() asm volatile("cp.async.commit_group;")
#define CPA_WAIT0()  asm volatile("cp.async.wait_group 0;")

// bf16 round-to-nearest split
__device__ __forceinline__ void bf16split(float f, uint32_t& hb, uint32_t& lb){
    uint32_t u = __float_as_uint(f);
    hb = (u + 0x7FFFu + ((u >> 16) & 1u)) >> 16;
    float hf = __uint_as_float(hb << 16);
    uint32_t lu = __float_as_uint(f - hf);
    lb = (lu + 0x7FFFu + ((lu >> 16) & 1u)) >> 16;
}
__device__ __forceinline__ float bf16f(unsigned short b){
    return __uint_as_float(((uint32_t)b) << 16);
}

// ---------------- zero accumulators + static rows of k_out B ----------------
__global__ void k_zero(const float* __restrict__ bout){
    int i = blockIdx.x*256 + threadIdx.x;       // grid 512*256 = 131072
    if (i < NB*32*DX) g_S[i] = 0.0f;
    if (i < NB*2048)  g_T[i] = 0.0f;
    if (i < NB*32)    g_ksum[i] = 0.0f;
    if (i < NB*16*512){                          // rows 32..47 of k_out B
        int b = i >> 13, rem = i & 8191;
        int k = 32 + (rem >> 9), d = rem & 511;
        unsigned short vh = 0, vl = 0;
        if (k == 32){
            uint32_t hb, lb; bf16split(bout[d], hb, lb);
            vh = (unsigned short)hb; vl = (unsigned short)lb;
        }
        g_Boh[((size_t)b*48 + k)*512 + d] = vh;
        g_Bol[((size_t)b*48 + k)*512 + d] = vl;
    }
}

// ---------------- fold weights -> bf16 hi/lo B chunks + bias ----------------
__global__ void k_combine(const float* __restrict__ Win, const float* __restrict__ bin,
                          const float* __restrict__ Wq,  const float* __restrict__ Wk){
    int idx = blockIdx.x*256 + threadIdx.x;
    if (idx < DX*64){
        int i = idx >> 6, j = idx & 63;          // i: K, j: col
        int h = (j >> 2) & 7, r = j & 3;
        const float* W = (j < 32) ? Wq : Wk;
        float s = 0.f;
        #pragma unroll 8
        for (int d = 0; d < 64; d++) s += Win[(size_t)i*DX + h*64 + d] * W[d*4 + r];
        uint32_t hb, lb; bf16split(s, hb, lb);
        int ch = i >> 6;
        int off = ch*4096 + (i & 63)*64 + j;     // [ch][k][n] row-major
        g_B1h[off] = (unsigned short)hb;
        g_B1l[off] = (unsigned short)lb;
    } else if (idx < DX*64 + 64){
        int j = idx - DX*64;
        int h = (j >> 2) & 7, r = j & 3;
        const float* W = (j < 32) ? Wq : Wk;
        float s = 0.f;
        #pragma unroll 8
        for (int d = 0; d < 64; d++) s += bin[h*64 + d] * W[d*4 + r];
        g_bqk[j] = s;
    }
}

// ---------------- main kernel: wmma logits + softmax/exp + wmma S accum ----
// bytes: AH[0,18432) AL[18432,36864) BH[36864,46080) BL[46080,55296)
//        Cs fp32 [128][72] reuses [0,36864)
//        pass3 Ss fp32 [32][72] reuses [36864,46080)
//        EH[55296,64000) EL[64000,72704)  (ekT [32][136] bf16)
//        bqs[72704,72960)
#define SM_MAIN 72960

__global__ __launch_bounds__(256, 2)
void k_main(const float* __restrict__ x){
    extern __shared__ __align__(1024) unsigned char smraw[];
    const uint32_t AH = 0, AL = 18432, BH = 36864, BL = 46080;
    const uint32_t EH = 55296, EL = 64000, BQ = 72704;
    float* Cs  = (float*)(smraw);
    float* Ss  = (float*)(smraw + BH);
    float* bqs = (float*)(smraw + BQ);

    const int tid = threadIdx.x, wid = tid >> 5;
    const int blk = blockIdx.x, row0 = blk * MT, b = blk >> 7;

    if (tid < 64) bqs[tid] = g_bqk[tid];

    // ============ pass 1: logits[128x64] = x @ Wqkc via wmma bf16 ============
    float4 xr[8];
    #define LDGX(ch) { _Pragma("unroll") for (int i = 0; i < 8; i++){ \
        int idx = tid + i*256; int r = idx >> 4, c = idx & 15; \
        xr[i] = *(const float4*)&x[(size_t)(row0 + r)*DX + (ch)*64 + c*4]; } }
    #define CONV_A() { _Pragma("unroll") for (int i = 0; i < 8; i++){ \
        int idx = tid + i*256; int r = idx >> 4, c = idx & 15; \
        float f[4] = {xr[i].x, xr[i].y, xr[i].z, xr[i].w}; \
        uint32_t hb[4], lb[4]; \
        _Pragma("unroll") for (int t = 0; t < 4; t++) bf16split(f[t], hb[t], lb[t]); \
        uint2 hp = make_uint2(hb[0] | (hb[1] << 16), hb[2] | (hb[3] << 16)); \
        uint2 lp = make_uint2(lb[0] | (lb[1] << 16), lb[2] | (lb[3] << 16)); \
        uint32_t off = (uint32_t)(r*72 + c*4)*2u; \
        *(uint2*)(smraw + AH + off) = hp; \
        *(uint2*)(smraw + AL + off) = lp; } }

    {
        wmma::fragment<wmma::accumulator,16,16,16,float> acc[4];
        #pragma unroll
        for (int nt = 0; nt < 4; nt++) wmma::fill_fragment(acc[nt], 0.0f);
        const unsigned sbase = smem_u32(smraw);

        LDGX(0);
        #pragma unroll 1
        for (int ch = 0; ch < 8; ch++){
            if (ch) __syncthreads();
            CONV_A();
            {   // stage B chunk [64k][64n] -> smem [64][72] hi/lo
                const unsigned short* gh = g_B1h + ch*4096;
                const unsigned short* gl = g_B1l + ch*4096;
                #pragma unroll
                for (int i = 0; i < 2; i++){
                    int idx = tid + i*256;
                    int k = idx >> 3, c8 = idx & 7;
                    uint32_t doff = (uint32_t)(k*72 + c8*8)*2u;
                    cpa16(sbase + BH + doff, gh + k*64 + c8*8);
                    cpa16(sbase + BL + doff, gl + k*64 + c8*8);
                }
                CPA_COMMIT();
            }
            if (ch < 7) LDGX(ch + 1);
            CPA_WAIT0();
            __syncthreads();

            const __nv_bfloat16* Ahp = (const __nv_bfloat16*)(smraw + AH) + wid*16*72;
            const __nv_bfloat16* Alp = (const __nv_bfloat16*)(smraw + AL) + wid*16*72;
            const __nv_bfloat16* Bhp = (const __nv_bfloat16*)(smraw + BH);
            const __nv_bfloat16* Blp = (const __nv_bfloat16*)(smraw + BL);
            #pragma unroll
            for (int ks = 0; ks < 4; ks++){
                wmma::fragment<wmma::matrix_a,16,16,16,__nv_bfloat16,wmma::row_major> ah, al;
                wmma::load_matrix_sync(ah, Ahp + ks*16, 72);
                wmma::load_matrix_sync(al, Alp + ks*16, 72);
                #pragma unroll
                for (int nt = 0; nt < 4; nt++){
                    wmma::fragment<wmma::matrix_b,16,16,16,__nv_bfloat16,wmma::row_major> bh, bl;
                    wmma::load_matrix_sync(bh, Bhp + ks*16*72 + nt*16, 72);
                    wmma::load_matrix_sync(bl, Blp + ks*16*72 + nt*16, 72);
                    wmma::mma_sync(acc[nt], ah, bh, acc[nt]);
                    wmma::mma_sync(acc[nt], ah, bl, acc[nt]);
                    wmma::mma_sync(acc[nt], al, bh, acc[nt]);
                }
            }
        }
        __syncthreads();
        #pragma unroll
        for (int nt = 0; nt < 4; nt++)
            wmma::store_matrix_sync(Cs + wid*16*72 + nt*16, acc[nt], 72, wmma::mem_row_major);
        __syncthreads();
    }

    // ============ epilogue: softmax(q) -> g_q ; exp(k) -> ekT (bf16 hi/lo) ====
    if (tid < 128){
        const int r = tid;
        const float* crow = Cs + r*72;
        size_t n = (size_t)row0 + r;
        #pragma unroll
        for (int h = 0; h < 8; h++){
            float v0 = crow[h*4+0] + bqs[h*4+0];
            float v1 = crow[h*4+1] + bqs[h*4+1];
            float v2 = crow[h*4+2] + bqs[h*4+2];
            float v3 = crow[h*4+3] + bqs[h*4+3];
            float m = fmaxf(fmaxf(v0, v1), fmaxf(v2, v3));
            float e0 = expf(v0-m), e1 = expf(v1-m), e2 = expf(v2-m), e3 = expf(v3-m);
            float inv = 1.0f/(e0+e1+e2+e3);
            float4 qv; qv.x = e0*inv; qv.y = e1*inv; qv.z = e2*inv; qv.w = e3*inv;
            *(float4*)&g_q[n*32 + h*4] = qv;
        }
        #pragma unroll
        for (int j = 0; j < 32; j++){
            float e = expf(crow[32 + j] + bqs[32 + j]);
            uint32_t hb, lb; bf16split(e, hb, lb);
            *(unsigned short*)(smraw + EH + (j*136 + r)*2u) = (unsigned short)hb;
            *(unsigned short*)(smraw + EL + (j*136 + r)*2u) = (unsigned short)lb;
        }
    }
    __syncthreads();

    // ksum partials (hi+lo sum in fp32 = exactly the E used in the MMA)
    if (tid < 32){
        const unsigned short* eh = (const unsigned short*)(smraw + EH) + tid*136;
        const unsigned short* el = (const unsigned short*)(smraw + EL) + tid*136;
        float s = 0.f;
        #pragma unroll 8
        for (int r = 0; r < 128; r++) s += bf16f(eh[r]) + bf16f(el[r]);
        atomicAdd(&g_ksum[b*32 + tid], s);
    }

    // ============ pass 3: S += ekT @ x via wmma (chunked over 64 cols) ========
    // warp tile: mt = wid>>2 (2 M-tiles), nt = wid&3 (4 N-tiles)
    const int mt = wid >> 2, nt = wid & 3;
    LDGX(0);
    #pragma unroll 1
    for (int ch = 0; ch < 8; ch++){
        if (ch) __syncthreads();      // prior atomics done reading Ss; AH/AL free
        CONV_A();
        if (ch < 7) LDGX(ch + 1);
        __syncthreads();

        wmma::fragment<wmma::accumulator,16,16,16,float> sacc;
        wmma::fill_fragment(sacc, 0.0f);
        const __nv_bfloat16* Ehp = (const __nv_bfloat16*)(smraw + EH) + mt*16*136;
        const __nv_bfloat16* Elp = (const __nv_bfloat16*)(smraw + EL) + mt*16*136;
        const __nv_bfloat16* Xhp = (const __nv_bfloat16*)(smraw + AH) + nt*16;
        const __nv_bfloat16* Xlp = (const __nv_bfloat16*)(smraw + AL) + nt*16;
        #pragma unroll
        for (int ks = 0; ks < 8; ks++){
            wmma::fragment<wmma::matrix_a,16,16,16,__nv_bfloat16,wmma::row_major> eh, el;
            wmma::load_matrix_sync(eh, Ehp + ks*16, 136);
            wmma::load_matrix_sync(el, Elp + ks*16, 136);
            wmma::fragment<wmma::matrix_b,16,16,16,__nv_bfloat16,wmma::row_major> xh, xl;
            wmma::load_matrix_sync(xh, Xhp + ks*16*72, 72);
            wmma::load_matrix_sync(xl, Xlp + ks*16*72, 72);
            wmma::mma_sync(sacc, eh, xh, sacc);
            wmma::mma_sync(sacc, eh, xl, sacc);
            wmma::mma_sync(sacc, el, xh, sacc);
        }
        __syncthreads();              // Cs/AH region still live? Ss region free after prev atomics
        wmma::store_matrix_sync(Ss + mt*16*72 + nt*16, sacc, 72, wmma::mem_row_major);
        __syncthreads();

        // atomics: 8 consecutive floats per thread
        {
            const int hr = tid >> 3, c0 = (tid & 7)*8;
            float* Sb = &g_S[b*16384 + hr*512 + ch*64 + c0];
            const float* sp = &Ss[hr*72 + c0];
            #pragma unroll
            for (int i = 0; i < 8; i++) atomicAdd(&Sb[i], sp[i]);
        }
    }
    #undef LDGX
    #undef CONV_A
}

// ---------------- T += S @ Win(head cols), split-K x8 ----------------
__global__ void k_T(const float* __restrict__ Win){
    __shared__ float Ss[4*64];
    const int bh = blockIdx.x >> 3, ks = blockIdx.x & 7;
    const int b = bh >> 3, h = bh & 7;
    const int tid = threadIdx.x;
    const int i0 = ks * 64;
    if (tid < 256){
        int r = tid >> 6, i = tid & 63;
        Ss[r*64 + i] = g_S[b*16384 + (h*4 + r)*512 + i0 + i];
    }
    __syncthreads();
    const int r = tid >> 6, d = tid & 63;
    const float* W = &Win[(size_t)i0*DX + h*64 + d];
    float s = 0.f;
    #pragma unroll 16
    for (int i = 0; i < 64; i++) s += Ss[r*64 + i] * W[(size_t)i*DX];
    atomicAdd(&g_T[b*2048 + (h*4 + r)*64 + d], s);
}

// ---------------- kv_norm = ((T + ksum*bin) @ Wv) / ksum ----------------
__global__ void k_kv(const float* __restrict__ Wv, const float* __restrict__ bin){
    __shared__ float Ts[2048], Wvs[4096], ks[32];
    int b = blockIdx.x, tid = threadIdx.x;
    if (tid < 32) ks[tid] = g_ksum[b*32 + tid];
    for (int i = tid; i < 4096; i += 256) Wvs[i] = Wv[i];
    __syncthreads();
    for (int i = tid; i < 2048; i += 256)
        Ts[i] = g_T[b*2048 + i] + ks[i >> 6] * bin[(i >> 8)*64 + (i & 63)];
    __syncthreads();
    int hr = tid >> 3, cs = tid & 7;
    float acc[8] = {0,0,0,0,0,0,0,0};
    #pragma unroll 4
    for (int d = 0; d < 64; d++){
        float t = Ts[hr*64 + d];
        #pragma unroll
        for (int c = 0; c < 8; c++) acc[c] += t * Wvs[d*64 + cs*8 + c];
    }
    float inv = 1.0f / ks[hr];
    #pragma unroll
    for (int c = 0; c < 8; c++) g_kvn[b*2048 + hr*64 + cs*8 + c] = acc[c] * inv;
}

// ---------------- M2 = kv_norm @ Wout -> bf16 hi/lo rows 0..31 of k_out B ----
__global__ void k_M2(const float* __restrict__ Wout){
    __shared__ float kvs[2048];
    int b = blockIdx.x >> 2, q4 = blockIdx.x & 3;
    int tid = threadIdx.x;
    for (int i = tid; i < 2048; i += 256) kvs[i] = g_kvn[b*2048 + i];
    __syncthreads();
    int hr = tid >> 3, dg = tid & 7, h = hr >> 2;
    int dout0 = q4*128 + dg*16;
    float acc[16];
    #pragma unroll
    for (int i = 0; i < 16; i++) acc[i] = 0.f;
    #pragma unroll 2
    for (int c = 0; c < 64; c++){
        float kv = kvs[hr*64 + c];
        const float* wrow = &Wout[(size_t)(h*64 + c)*DX + dout0];
        #pragma unroll
        for (int i = 0; i < 16; i++) acc[i] += kv * wrow[i];
    }
    size_t base = ((size_t)b*48 + hr)*512 + dout0;   // B row = hr (K index)
    #pragma unroll
    for (int i = 0; i < 16; i++){
        uint32_t hb, lb; bf16split(acc[i], hb, lb);
        g_Boh[base + i] = (unsigned short)hb;
        g_Bol[base + i] = (unsigned short)lb;
    }
}

// ---------------- output: out = [qhat|1] @ [M2;bout] via wmma (bias in K) ----
// bytes: AH[0,14336) AL[14336,28672) BH[28672,54016) BL[54016,79360)
//   B half tile [48][264] bf16 per buffer (256 N-cols per half)
#define SM_OUT 79360

__global__ __launch_bounds__(256, 2)
void k_out(float* __restrict__ out){
    extern __shared__ __align__(1024) unsigned char smraw[];
    const uint32_t sbase = smem_u32(smraw);
    const uint32_t AH = 0, AL = 14336, BH = 28672, BL = 54016;

    const int tid = threadIdx.x, wid = tid >> 5;
    const int blk = blockIdx.x, row0 = blk * MT, b = blk >> 7;

    // build A [128][56]: cols 0..31 = qhat split, col 32 = 1, 33..55 = 0
    #pragma unroll
    for (int i = 0; i < 4; i++){
        int idx = tid + i*256; int r = idx >> 3, c = idx & 7;
        float4 q = *(const float4*)&g_q[((size_t)row0 + r)*32 + c*4];
        float f[4] = {q.x, q.y, q.z, q.w};
        uint32_t hb[4], lb[4];
        #pragma unroll
        for (int t = 0; t < 4; t++) bf16split(f[t], hb[t], lb[t]);
        uint2 hp = make_uint2(hb[0] | (hb[1] << 16), hb[2] | (hb[3] << 16));
        uint2 lp = make_uint2(lb[0] | (lb[1] << 16), lb[2] | (lb[3] << 16));
        uint32_t off = (uint32_t)(r*56 + c*4)*2u;
        *(uint2*)(smraw + AH + off) = hp;
        *(uint2*)(smraw + AL + off) = lp;
    }
    #pragma unroll
    for (int i = 0; i < 6; i++){
        int idx = tid + i*256;                    // 1536 uint32: cols 32..55
        int r = idx / 12, c2 = idx % 12;
        uint32_t off = (uint32_t)(r*56 + 32 + c2*2)*2u;
        *(uint32_t*)(smraw + AH + off) = (c2 == 0) ? 0x00003F80u : 0u;  // bf16(1.0)
        *(uint32_t*)(smraw + AL + off) = 0u;
    }

    const __nv_bfloat16* Ahp = (const __nv_bfloat16*)(smraw + AH) + wid*16*56;
    const __nv_bfloat16* Alp = (const __nv_bfloat16*)(smraw + AL) + wid*16*56;

    #pragma unroll 1
    for (int half = 0; half < 2; half++){
        // stage B half [48][256] -> smem [48][264] hi/lo
        {
            const unsigned short* gh = g_Boh + (size_t)b*48*512 + half*256;
            const unsigned short* gl = g_Bol + (size_t)b*48*512 + half*256;
            #pragma unroll
            for (int i = 0; i < 6; i++){
                int idx = tid + i*256;             // 1536 groups of 8 bf16
                int k = idx >> 5, c8 = idx & 31;
                uint32_t doff = (uint32_t)(k*264 + c8*8)*2u;
                cpa16(sbase + BH + doff, gh + (size_t)k*512 + c8*8);
                cpa16(sbase + BL + doff, gl + (size_t)k*512 + c8*8);
            }
            CPA_COMMIT(); CPA_WAIT0();
        }
        __syncthreads();

        const __nv_bfloat16* Bhp = (const __nv_bfloat16*)(smraw + BH);
        const __nv_bfloat16* Blp = (const __nv_bfloat16*)(smraw + BL);
        #pragma unroll 1
        for (int npass = 0; npass < 2; npass++){
            wmma::fragment<wmma::accumulator,16,16,16,float> acc[8];
            #pragma unroll
            for (int nt = 0; nt < 8; nt++) wmma::fill_fragment(acc[nt], 0.0f);
            #pragma unroll
            for (int ksi = 0; ksi < 3; ksi++){
                wmma::fragment<wmma::matrix_a,16,16,16,__nv_bfloat16,wmma::row_major> ah, al;
                wmma::load_matrix_sync(ah, Ahp + ksi*16, 56);
                wmma::load_matrix_sync(al, Alp + ksi*16, 56);
                #pragma unroll
                for (int nt = 0; nt < 8; nt++){
                    int n0 = npass*128 + nt*16;
                    wmma::fragment<wmma::matrix_b,16,16,16,__nv_bfloat16,wmma::row_major> bh, bl;
                    wmma::load_matrix_sync(bh, Bhp + ksi*16*264 + n0, 264);
                    wmma::load_matrix_sync(bl, Blp + ksi*16*264 + n0, 264);
                    wmma::mma_sync(acc[nt], ah, bh, acc[nt]);
                    wmma::mma_sync(acc[nt], ah, bl, acc[nt]);
                    wmma::mma_sync(acc[nt], al, bh, acc[nt]);
                }
            }
            float* orow = out + ((size_t)row0 + wid*16)*DX + half*256 + npass*128;
            #pragma unroll
            for (int nt = 0; nt < 8; nt++)
                wmma::store_matrix_sync(orow + nt*16, acc[nt], DX, wmma::mem_row_major);
        }
        __syncthreads();   // before restaging B
    }
}

// ---------------- launch ----------------
extern "C" void kernel_launch(void* const* d_in, const int* in_sizes, int n_in,
                              void* d_out, int out_size)
{
    const float* x    = (const float*)d_in[0];
    const float* Win  = (const float*)d_in[1];
    const float* bin  = (const float*)d_in[2];
    const float* Wq   = (const float*)d_in[3];
    const float* Wk   = (const float*)d_in[4];
    const float* Wv   = (const float*)d_in[5];
    const float* Wout = (const float*)d_in[6];
    const float* bout = (const float*)d_in[7];
    float* out = (float*)d_out;

    cudaFuncSetAttribute(k_main, cudaFuncAttributeMaxDynamicSharedMemorySize, SM_MAIN);
    cudaFuncSetAttribute(k_out,  cudaFuncAttributeMaxDynamicSharedMemorySize, SM_OUT);

    k_zero<<<512, 256>>>(bout);
    k_combine<<<129, 256>>>(Win, bin, Wq, Wk);
    k_main<<<GRID_MAIN, 256, SM_MAIN>>>(x);
    k_T<<<512, 256>>>(Win);
    k_kv<<<8, 256>>>(Wv, bin);
    k_M2<<<32, 256>>>(Wout);
    k_out<<<GRID_MAIN, 256, SM_OUT>>>(out);
}